// round 8
// baseline (speedup 1.0000x reference)
#include <cuda_runtime.h>
#include <math.h>

// Problem constants
#define Bsz 64
#define Lsz 24
#define Dsz 512
#define Hsz 512
#define NSLOT (Bsz*Lsz)   // 1536 node slots
#define UWLD 5120         // per-slot row: [u(2560) | w(2560)]
#define HCLD 1024         // per-slot row: [h(512) | c(512)]
#define GRID_P 148        // persistent grid (<= SM count, fully resident)

// Static scratch (no allocations allowed)
__device__ __align__(16) float g_HC[NSLOT*HCLD];   // 6.3 MB
__device__ __align__(16) float g_UW[NSLOT*UWLD];   // 31.5 MB
__device__ __align__(16) float g_NH[Bsz*Hsz];      // merged-node h, compact per batch
__device__ float g_scores[Bsz*Lsz];
__device__ int   g_rowmap[Bsz];                    // slot to receive updated u/w (-1 = skip)

// Grid barrier state (reset every launch by k_reset)
__device__ unsigned g_barcnt;
__device__ unsigned g_barsense;

__global__ void k_reset() { g_barcnt = 0u; g_barsense = 0u; }

__device__ __forceinline__ void grid_bar(unsigned& lsense) {
    __syncthreads();
    if (threadIdx.x == 0) {
        unsigned want = lsense ^ 1u;
        lsense = want;
        __threadfence();
        unsigned arrived = atomicAdd(&g_barcnt, 1u) + 1u;
        if (arrived == gridDim.x) {
            g_barcnt = 0u;
            __threadfence();
            atomicExch(&g_barsense, want);
        } else {
            while (*(volatile unsigned*)&g_barsense != want) __nanosleep(64);
        }
        __threadfence();
    }
    __syncthreads();
}

__device__ __forceinline__ float sigf(float x) { return 1.0f/(1.0f+expf(-x)); }

// Gate math for pair (slot l, slot r) at hidden dim t. v = u_l + w_r
// (comp_b folded into u). UW read via __ldcg: rows are rewritten by other SMs
// within the persistent kernel (L1 not coherent). HC slots are only ever
// written by this batch's own block (or a prior launch) -> plain loads OK.
__device__ __forceinline__ void pair_gates(int l, int r, int t, float& nh, float& nc) {
    const float* u = g_UW + (size_t)l*UWLD;
    const float* w = g_UW + (size_t)r*UWLD + 2560;
    float gi  = __ldcg(u + t)        + __ldcg(w + t);
    float gfl = __ldcg(u + 512 + t)  + __ldcg(w + 512 + t);
    float gfr = __ldcg(u + 1024 + t) + __ldcg(w + 1024 + t);
    float gu  = __ldcg(u + 1536 + t) + __ldcg(w + 1536 + t);
    float go  = __ldcg(u + 2048 + t) + __ldcg(w + 2048 + t);
    float cl  = g_HC[(size_t)l*HCLD + 512 + t];
    float cr  = g_HC[(size_t)r*HCLD + 512 + t];
    nc = cl*sigf(gfl + 1.0f) + cr*sigf(gfr + 1.0f) + tanhf(gu)*sigf(gi);
    nh = sigf(go)*tanhf(nc);
}

// ---------------------------------------------------------------------------
// NT GEMM: C[m,n] = sum_k A[m,k]*B[n,k] (+bias). Tile BMxBN, microtile TMxTN.
// DUAL: virtual B = [comp_W[:, :512] ; comp_W[:, 512:]] stacked (n<2560 -> Wl,
// else Wr), bias applied to first half only. BK=16, K%16==0, TN%4==0.
// ---------------------------------------------------------------------------
template<int BM, int BN, int TM, int TN, bool DUAL>
__global__ void __launch_bounds__((BM/TM)*(BN/TN))
gemm_nt(const float* __restrict__ A, int lda,
        const float* __restrict__ Bm, int ldb,
        const float* __restrict__ bias,
        float* __restrict__ C, int ldc, int K)
{
    constexpr int BK = 16;
    constexpr int NTH = (BM/TM)*(BN/TN);
    constexpr int NXT = BN/TN;
    __shared__ float As[BK][BM];
    __shared__ float Bs[BK][BN];
    const int tid = threadIdx.x;
    const int m0 = blockIdx.y * BM;
    const int n0 = blockIdx.x * BN;
    const int tx = tid % NXT;
    const int ty = tid / NXT;
    float acc[TM][TN];
    #pragma unroll
    for (int i = 0; i < TM; i++)
        #pragma unroll
        for (int j = 0; j < TN; j++) acc[i][j] = 0.f;

    for (int k0 = 0; k0 < K; k0 += BK) {
        #pragma unroll
        for (int idx = tid; idx < BM*BK/4; idx += NTH) {
            int m  = idx >> 2;
            int kq = idx & 3;
            float4 a = *(const float4*)(A + (size_t)(m0+m)*lda + k0 + kq*4);
            As[kq*4+0][m] = a.x; As[kq*4+1][m] = a.y;
            As[kq*4+2][m] = a.z; As[kq*4+3][m] = a.w;
        }
        #pragma unroll
        for (int idx = tid; idx < BN*BK/4; idx += NTH) {
            int n  = idx >> 2;
            int kq = idx & 3;
            int gn = n0 + n;
            const float* bp;
            if (DUAL)
                bp = (gn < 2560) ? (Bm + (size_t)gn*1024 + k0 + kq*4)
                                 : (Bm + (size_t)(gn-2560)*1024 + 512 + k0 + kq*4);
            else
                bp = Bm + (size_t)gn*ldb + k0 + kq*4;
            float4 bv = *(const float4*)bp;
            Bs[kq*4+0][n] = bv.x; Bs[kq*4+1][n] = bv.y;
            Bs[kq*4+2][n] = bv.z; Bs[kq*4+3][n] = bv.w;
        }
        __syncthreads();
        #pragma unroll
        for (int k = 0; k < BK; k++) {
            float am[TM], bn_[TN];
            #pragma unroll
            for (int q = 0; q < TM/4; q++) {
                float4 av = *(const float4*)&As[k][ty*TM + q*4];
                am[q*4+0] = av.x; am[q*4+1] = av.y;
                am[q*4+2] = av.z; am[q*4+3] = av.w;
            }
            #pragma unroll
            for (int q = 0; q < TN/4; q++) {
                float4 bv = *(const float4*)&Bs[k][tx*TN + q*4];
                bn_[q*4+0] = bv.x; bn_[q*4+1] = bv.y;
                bn_[q*4+2] = bv.z; bn_[q*4+3] = bv.w;
            }
            #pragma unroll
            for (int i = 0; i < TM; i++)
                #pragma unroll
                for (int j = 0; j < TN; j++)
                    acc[i][j] += am[i]*bn_[j];
        }
        __syncthreads();
    }

    #pragma unroll
    for (int i = 0; i < TM; i++) {
        int m = m0 + ty*TM + i;
        #pragma unroll
        for (int q = 0; q < TN/4; q++) {
            int gn = n0 + tx*TN + q*4;
            float b0=0.f,b1=0.f,b2=0.f,b3=0.f;
            if (bias && (!DUAL || gn < 2560)) {
                b0 = bias[gn]; b1 = bias[gn+1]; b2 = bias[gn+2]; b3 = bias[gn+3];
            }
            float4 o;
            o.x = acc[i][q*4+0] + b0; o.y = acc[i][q*4+1] + b1;
            o.z = acc[i][q*4+2] + b2; o.w = acc[i][q*4+3] + b3;
            *(float4*)(C + (size_t)m*ldc + gn) = o;
        }
    }
}

// ---------------------------------------------------------------------------
// Iteration 0: score all 23 adjacent pairs (slots are identity at iter 0).
__global__ void k_score_all(const float* __restrict__ q) {
    int j = blockIdx.x, b = blockIdx.y;
    int l = b*Lsz + j, r = b*Lsz + j + 1;
    float part = 0.f;
    for (int t = threadIdx.x; t < 512; t += 256) {
        float nh, nc; pair_gates(l, r, t, nh, nc);
        part += nh * q[t];
    }
    __shared__ float red[8];
    #pragma unroll
    for (int o = 16; o; o >>= 1) part += __shfl_down_sync(0xffffffffu, part, o);
    if ((threadIdx.x & 31) == 0) red[threadIdx.x >> 5] = part;
    __syncthreads();
    if (threadIdx.x == 0) {
        float s = 0.f;
        #pragma unroll
        for (int w = 0; w < 8; w++) s += red[w];
        g_scores[b*Lsz + j] = s;
    }
}

// ---------------------------------------------------------------------------
// Update-GEMM phase inside the persistent kernel: UW[rowmap[m]] gets the
// u|w projection of g_NH. Blocks 0..127 each own a 64x40 tile of N=5120.
// Threads: all 256 load smem; tid<160 compute 4x4 microtiles.
__device__ void gemm_update_phase(int bid,
                                  const float* __restrict__ comp_W,
                                  const float* __restrict__ comp_b,
                                  int* s_rm)
{
    __shared__ float As[16][64];   // 4 KB
    __shared__ float Bs[16][40];   // 2.5 KB
    const int tid = threadIdx.x;
    if (tid < Bsz) s_rm[tid] = __ldcg(&g_rowmap[tid]);
    if (bid >= 128) return;        // idle blocks: caller's grid_bar has the syncs
    const int n0 = bid * 40;
    const int tx = tid % 10;
    const int ty = tid / 10;       // 0..15 for tid<160
    float acc[4][4] = {};

    for (int k0 = 0; k0 < 512; k0 += 16) {
        {   // A tile: 64x16 from g_NH (written cross-SM this launch -> ldcg)
            int m  = tid >> 2;
            int kq = tid & 3;
            float4 a = __ldcg((const float4*)(g_NH + (size_t)m*512 + k0 + kq*4));
            As[kq*4+0][m] = a.x; As[kq*4+1][m] = a.y;
            As[kq*4+2][m] = a.z; As[kq*4+3][m] = a.w;
        }
        if (tid < 160) {  // B tile: 40x16 (dual comp_W mapping, read-only input)
            int n  = tid >> 2;
            int kq = tid & 3;
            int gn = n0 + n;
            const float* bp = (gn < 2560)
                ? (comp_W + (size_t)gn*1024 + k0 + kq*4)
                : (comp_W + (size_t)(gn-2560)*1024 + 512 + k0 + kq*4);
            float4 bv = *(const float4*)bp;
            Bs[kq*4+0][n] = bv.x; Bs[kq*4+1][n] = bv.y;
            Bs[kq*4+2][n] = bv.z; Bs[kq*4+3][n] = bv.w;
        }
        __syncthreads();
        if (tid < 160) {
            #pragma unroll
            for (int k = 0; k < 16; k++) {
                float4 av = *(const float4*)&As[k][ty*4];
                float4 bv = *(const float4*)&Bs[k][tx*4];
                float am[4] = {av.x, av.y, av.z, av.w};
                float bn_[4] = {bv.x, bv.y, bv.z, bv.w};
                #pragma unroll
                for (int i = 0; i < 4; i++)
                    #pragma unroll
                    for (int j = 0; j < 4; j++)
                        acc[i][j] += am[i]*bn_[j];
            }
        }
        __syncthreads();
    }

    if (tid < 160) {
        int gn = n0 + tx*4;
        float b0=0.f,b1=0.f,b2=0.f,b3=0.f;
        if (gn < 2560) { b0=comp_b[gn]; b1=comp_b[gn+1]; b2=comp_b[gn+2]; b3=comp_b[gn+3]; }
        #pragma unroll
        for (int i = 0; i < 4; i++) {
            int orow = s_rm[ty*4 + i];
            if (orow < 0) continue;
            float4 o;
            o.x = acc[i][0] + b0; o.y = acc[i][1] + b1;
            o.z = acc[i][2] + b2; o.w = acc[i][3] + b3;
            *(float4*)(g_UW + (size_t)orow*UWLD + gn) = o;
        }
    }
}

// ---------------------------------------------------------------------------
// Persistent loop: 23 step phases + 22 update-GEMM phases, grid barriers.
// Blocks 0..63 own batch b's tree state in shared memory.
__global__ void __launch_bounds__(256, 1)
k_loop(const float* __restrict__ q, const int* __restrict__ length,
       float* __restrict__ out,
       const float* __restrict__ comp_W, const float* __restrict__ comp_b)
{
    const int bid = blockIdx.x;
    const int tid = threadIdx.x;
    unsigned lsense = 0;
    __shared__ int   s_pos[Lsz];
    __shared__ float s_sc[Lsz];
    __shared__ float red[2][4];
    __shared__ int   s_k, s_len;
    __shared__ int   s_rm[Bsz];
    const bool stepB = (bid < Bsz);
    const int b = bid;

    if (stepB) {
        if (tid == 0) { s_len = length[b]; s_k = -1; }
        if (tid < Lsz) s_pos[tid] = b*Lsz + tid;
        if (tid < Lsz-1) s_sc[tid] = g_scores[b*Lsz + tid];  // from k_score_all
    }
    __syncthreads();

    for (int iter = 0; iter < Lsz-1; iter++) {
        if (stepB) {
            int nvalid = s_len - 1 - iter;
            if (iter > 0) {
                int kp = s_k;                       // previous merge position
                if (kp >= 0) {
                    int half = tid >> 7;            // rescore pairs kp-1, kp
                    int ht   = tid & 127;
                    int jj = kp - 1 + half;
                    bool act = (jj >= 0) && (jj < nvalid);
                    float part = 0.f;
                    if (act) {
                        int l = s_pos[jj], r = s_pos[jj+1];
                        #pragma unroll
                        for (int s = 0; s < 4; s++) {
                            int t = ht + s*128;
                            float nh, nc; pair_gates(l, r, t, nh, nc);
                            part += nh * q[t];
                        }
                    }
                    #pragma unroll
                    for (int o = 16; o; o >>= 1) part += __shfl_down_sync(0xffffffffu, part, o);
                    if ((ht & 31) == 0) red[half][ht >> 5] = part;
                    __syncthreads();
                    if (ht == 0 && act)
                        s_sc[jj] = red[half][0] + red[half][1] + red[half][2] + red[half][3];
                    __syncthreads();
                }
            }
            // argmax with first-index tie-break (matches jnp.argmax)
            if (tid < 32) {
                float v = (tid < nvalid) ? s_sc[tid] : -1e9f;
                int idx = tid;
                #pragma unroll
                for (int o = 16; o; o >>= 1) {
                    float v2 = __shfl_down_sync(0xffffffffu, v, o);
                    int  i2  = __shfl_down_sync(0xffffffffu, idx, o);
                    if (v2 > v || (v2 == v && i2 < idx)) { v = v2; idx = i2; }
                }
                if (tid == 0) s_k = (nvalid > 0) ? idx : -1;
            }
            __syncthreads();
            int k = s_k;
            if (k >= 0) {
                int l = s_pos[k], r = s_pos[k+1];
                for (int t = tid; t < 512; t += 256) {
                    float nh, nc; pair_gates(l, r, t, nh, nc);
                    g_HC[(size_t)l*HCLD + t]       = nh;   // merged node reuses left slot
                    g_HC[(size_t)l*HCLD + 512 + t] = nc;
                    g_NH[b*512 + t] = nh;                  // staged for update GEMM
                }
                __syncthreads();
                if (tid == 0) {
                    g_rowmap[b] = l;
                    for (int j = k+1; j < Lsz-1; j++) {    // shift logical lists
                        s_pos[j] = s_pos[j+1];
                        s_sc[j]  = s_sc[j+1];
                    }
                }
            } else {
                if (tid == 0) g_rowmap[b] = -1;            // frozen batch
            }
        }
        grid_bar(lsense);
        if (iter < Lsz-2) {
            gemm_update_phase(bid, comp_W, comp_b, s_rm);
            grid_bar(lsense);
        }
    }

    if (stepB) {
        int slot = s_pos[0];
        for (int t = tid; t < 512; t += 256)
            out[b*512 + t] = g_HC[(size_t)slot*HCLD + t];
    }
}

// ---------------------------------------------------------------------------
extern "C" void kernel_launch(void* const* d_in, const int* in_sizes, int n_in,
                              void* d_out, int out_size) {
    const float* inp    = (const float*)d_in[0];
    const int*   length = (const int*)  d_in[1];
    const float* word_W = (const float*)d_in[2];
    const float* word_b = (const float*)d_in[3];
    const float* comp_W = (const float*)d_in[4];
    const float* comp_b = (const float*)d_in[5];
    const float* q      = (const float*)d_in[6];
    float* out = (float*)d_out;
    (void)in_sizes; (void)n_in; (void)out_size;

    float *HC = nullptr, *UW = nullptr;
    cudaGetSymbolAddress((void**)&HC, g_HC);
    cudaGetSymbolAddress((void**)&UW, g_UW);

    k_reset<<<1, 1>>>();

    // hc = inp @ word_W.T + word_b  -> HC[slot][h|c]
    gemm_nt<128, 64, 8, 4, false><<<dim3(1024/64, NSLOT/128), 256>>>(
        inp, Dsz, word_W, Dsz, word_b, HC, HCLD, Dsz);

    // u|w projections for all 1536 leaf nodes (comp_b folded into u half)
    gemm_nt<128, 128, 8, 8, true><<<dim3(5120/128, NSLOT/128), 256>>>(
        HC, HCLD, comp_W, 0, comp_b, UW, UWLD, Hsz);

    k_score_all<<<dim3(Lsz-1, Bsz), 256>>>(q);

    // persistent loop: all 23 merges + 22 incremental u/w updates
    k_loop<<<GRID_P, 256>>>(q, length, out, comp_W, comp_b);
}

// round 9
// speedup vs baseline: 1.0458x; 1.0458x over previous
#include <cuda_runtime.h>
#include <math.h>

// Problem constants
#define Bsz 64
#define Lsz 24
#define Dsz 512
#define Hsz 512
#define NSLOT (Bsz*Lsz)   // 1536 node slots
#define UWLD 5120         // per-slot row: [u(2560) | w(2560)]
#define HCLD 1024         // per-slot row: [h(512) | c(512)]
#define GRID_P 148        // persistent grid (fully resident)
#define NTHR_P 320        // persistent block size (10 warps)

// Static scratch (no allocations allowed)
__device__ __align__(16) float g_HC[NSLOT*HCLD];   // 6.3 MB
__device__ __align__(16) float g_UW[NSLOT*UWLD];   // 31.5 MB
__device__ __align__(16) float g_NH[Bsz*Hsz];      // merged-node h, compact per batch
__device__ float g_scores[Bsz*Lsz];
__device__ int   g_rowmap[Bsz];                    // slot to receive updated u/w (-1 = skip)

// Grid barrier state (reset every launch by k_reset so graph replays stay in phase)
__device__ unsigned g_barcnt;
__device__ unsigned g_barsense;

__global__ void k_reset() { g_barcnt = 0u; g_barsense = 0u; }

__device__ __forceinline__ void grid_bar(unsigned& lsense) {
    __syncthreads();
    if (threadIdx.x == 0) {
        unsigned want = lsense ^ 1u;
        lsense = want;
        __threadfence();
        unsigned arrived = atomicAdd(&g_barcnt, 1u) + 1u;
        if (arrived == gridDim.x) {
            g_barcnt = 0u;
            __threadfence();
            atomicExch(&g_barsense, want);
        } else {
            while (*(volatile unsigned*)&g_barsense != want) __nanosleep(64);
        }
        __threadfence();
    }
    __syncthreads();
}

__device__ __forceinline__ float sigf(float x) { return 1.0f/(1.0f+expf(-x)); }

// Gate math for pair (slot l, slot r) at hidden dim t. v = u_l + w_r
// (comp_b folded into u). UW read via __ldcg: rows are rewritten by other SMs
// within the persistent kernel (L1 not coherent). HC slots are only ever
// written by this batch's own block (or a prior launch) -> plain loads OK.
__device__ __forceinline__ void pair_gates(int l, int r, int t, float& nh, float& nc) {
    const float* u = g_UW + (size_t)l*UWLD;
    const float* w = g_UW + (size_t)r*UWLD + 2560;
    float gi  = __ldcg(u + t)        + __ldcg(w + t);
    float gfl = __ldcg(u + 512 + t)  + __ldcg(w + 512 + t);
    float gfr = __ldcg(u + 1024 + t) + __ldcg(w + 1024 + t);
    float gu  = __ldcg(u + 1536 + t) + __ldcg(w + 1536 + t);
    float go  = __ldcg(u + 2048 + t) + __ldcg(w + 2048 + t);
    float cl  = g_HC[(size_t)l*HCLD + 512 + t];
    float cr  = g_HC[(size_t)r*HCLD + 512 + t];
    nc = cl*sigf(gfl + 1.0f) + cr*sigf(gfr + 1.0f) + tanhf(gu)*sigf(gi);
    nh = sigf(go)*tanhf(nc);
}

// ---------------------------------------------------------------------------
// NT GEMM: C[m,n] = sum_k A[m,k]*B[n,k] (+bias). Tile BMxBN, microtile TMxTN.
// DUAL: virtual B = [comp_W[:, :512] ; comp_W[:, 512:]] stacked (n<2560 -> Wl,
// else Wr), bias applied to first half only. BK=16, K%16==0, TN%4==0.
// ---------------------------------------------------------------------------
template<int BM, int BN, int TM, int TN, bool DUAL, int MINB>
__global__ void __launch_bounds__((BM/TM)*(BN/TN), MINB)
gemm_nt(const float* __restrict__ A, int lda,
        const float* __restrict__ Bm, int ldb,
        const float* __restrict__ bias,
        float* __restrict__ C, int ldc, int K)
{
    constexpr int BK = 16;
    constexpr int NTH = (BM/TM)*(BN/TN);
    constexpr int NXT = BN/TN;
    __shared__ float As[BK][BM];
    __shared__ float Bs[BK][BN];
    const int tid = threadIdx.x;
    const int m0 = blockIdx.y * BM;
    const int n0 = blockIdx.x * BN;
    const int tx = tid % NXT;
    const int ty = tid / NXT;
    float acc[TM][TN];
    #pragma unroll
    for (int i = 0; i < TM; i++)
        #pragma unroll
        for (int j = 0; j < TN; j++) acc[i][j] = 0.f;

    for (int k0 = 0; k0 < K; k0 += BK) {
        #pragma unroll
        for (int idx = tid; idx < BM*BK/4; idx += NTH) {
            int m  = idx >> 2;
            int kq = idx & 3;
            float4 a = *(const float4*)(A + (size_t)(m0+m)*lda + k0 + kq*4);
            As[kq*4+0][m] = a.x; As[kq*4+1][m] = a.y;
            As[kq*4+2][m] = a.z; As[kq*4+3][m] = a.w;
        }
        #pragma unroll
        for (int idx = tid; idx < BN*BK/4; idx += NTH) {
            int n  = idx >> 2;
            int kq = idx & 3;
            int gn = n0 + n;
            const float* bp;
            if (DUAL)
                bp = (gn < 2560) ? (Bm + (size_t)gn*1024 + k0 + kq*4)
                                 : (Bm + (size_t)(gn-2560)*1024 + 512 + k0 + kq*4);
            else
                bp = Bm + (size_t)gn*ldb + k0 + kq*4;
            float4 bv = *(const float4*)bp;
            Bs[kq*4+0][n] = bv.x; Bs[kq*4+1][n] = bv.y;
            Bs[kq*4+2][n] = bv.z; Bs[kq*4+3][n] = bv.w;
        }
        __syncthreads();
        #pragma unroll
        for (int k = 0; k < BK; k++) {
            float am[TM], bn_[TN];
            #pragma unroll
            for (int q = 0; q < TM/4; q++) {
                float4 av = *(const float4*)&As[k][ty*TM + q*4];
                am[q*4+0] = av.x; am[q*4+1] = av.y;
                am[q*4+2] = av.z; am[q*4+3] = av.w;
            }
            #pragma unroll
            for (int q = 0; q < TN/4; q++) {
                float4 bv = *(const float4*)&Bs[k][tx*TN + q*4];
                bn_[q*4+0] = bv.x; bn_[q*4+1] = bv.y;
                bn_[q*4+2] = bv.z; bn_[q*4+3] = bv.w;
            }
            #pragma unroll
            for (int i = 0; i < TM; i++)
                #pragma unroll
                for (int j = 0; j < TN; j++)
                    acc[i][j] += am[i]*bn_[j];
        }
        __syncthreads();
    }

    #pragma unroll
    for (int i = 0; i < TM; i++) {
        int m = m0 + ty*TM + i;
        #pragma unroll
        for (int q = 0; q < TN/4; q++) {
            int gn = n0 + tx*TN + q*4;
            float b0=0.f,b1=0.f,b2=0.f,b3=0.f;
            if (bias && (!DUAL || gn < 2560)) {
                b0 = bias[gn]; b1 = bias[gn+1]; b2 = bias[gn+2]; b3 = bias[gn+3];
            }
            float4 o;
            o.x = acc[i][q*4+0] + b0; o.y = acc[i][q*4+1] + b1;
            o.z = acc[i][q*4+2] + b2; o.w = acc[i][q*4+3] + b3;
            *(float4*)(C + (size_t)m*ldc + gn) = o;
        }
    }
}

// ---------------------------------------------------------------------------
// Iteration 0: score all 23 adjacent pairs (slots are identity at iter 0).
__global__ void k_score_all(const float* __restrict__ q) {
    int j = blockIdx.x, b = blockIdx.y;
    int l = b*Lsz + j, r = b*Lsz + j + 1;
    float part = 0.f;
    for (int t = threadIdx.x; t < 512; t += 256) {
        float nh, nc; pair_gates(l, r, t, nh, nc);
        part += nh * q[t];
    }
    __shared__ float red[8];
    #pragma unroll
    for (int o = 16; o; o >>= 1) part += __shfl_down_sync(0xffffffffu, part, o);
    if ((threadIdx.x & 31) == 0) red[threadIdx.x >> 5] = part;
    __syncthreads();
    if (threadIdx.x == 0) {
        float s = 0.f;
        #pragma unroll
        for (int w = 0; w < 8; w++) s += red[w];
        g_scores[b*Lsz + j] = s;
    }
}

// ---------------------------------------------------------------------------
// Update-GEMM phase: UW[rowmap[m]] <- u|w projection of g_NH[m].
// Blocks 0..127 own a 64x40 tile of N=5120. 320 threads, 2x4 microtile,
// all 10 warps compute. Double-buffered smem, one sync per K-chunk.
__device__ __forceinline__ void upd_load(int c, int buf, int n0, int tid,
                                         const float* __restrict__ comp_W,
                                         float As[2][16][64], float Bs[2][16][40])
{
    int k0 = c*16;
    if (tid < 256) {   // A tile: 64x16 from g_NH (cross-SM written -> ldcg)
        int m = tid >> 2, kq = tid & 3;
        float4 a = __ldcg((const float4*)(g_NH + (size_t)m*512 + k0 + kq*4));
        As[buf][kq*4+0][m] = a.x; As[buf][kq*4+1][m] = a.y;
        As[buf][kq*4+2][m] = a.z; As[buf][kq*4+3][m] = a.w;
    }
    if (tid < 160) {   // B tile: 40x16 (dual comp_W mapping, read-only)
        int n = tid >> 2, kq = tid & 3;
        int gn = n0 + n;
        const float* bp = (gn < 2560)
            ? (comp_W + (size_t)gn*1024 + k0 + kq*4)
            : (comp_W + (size_t)(gn-2560)*1024 + 512 + k0 + kq*4);
        float4 bv = *(const float4*)bp;
        Bs[buf][kq*4+0][n] = bv.x; Bs[buf][kq*4+1][n] = bv.y;
        Bs[buf][kq*4+2][n] = bv.z; Bs[buf][kq*4+3][n] = bv.w;
    }
}

__device__ void gemm_update_phase(int bid,
                                  const float* __restrict__ comp_W,
                                  const float* __restrict__ comp_b,
                                  int* s_rm,
                                  float As[2][16][64], float Bs[2][16][40])
{
    const int tid = threadIdx.x;
    if (tid < Bsz) s_rm[tid] = __ldcg(&g_rowmap[tid]);
    if (bid >= 128) return;        // idle blocks: caller's grid_bar has the syncs
    const int n0 = bid * 40;
    const int tx = tid % 10;       // 0..9  (4 n each)
    const int ty = tid / 10;       // 0..31 (2 m each)
    float acc[2][4] = {};

    upd_load(0, 0, n0, tid, comp_W, As, Bs);
    __syncthreads();
    #pragma unroll 1
    for (int c = 0; c < 32; c++) {
        int cur = c & 1;
        if (c + 1 < 32) upd_load(c + 1, cur ^ 1, n0, tid, comp_W, As, Bs);
        #pragma unroll
        for (int k = 0; k < 16; k++) {
            float2 av = *(const float2*)&As[cur][k][ty*2];
            float4 bv = *(const float4*)&Bs[cur][k][tx*4];
            acc[0][0] += av.x*bv.x; acc[0][1] += av.x*bv.y;
            acc[0][2] += av.x*bv.z; acc[0][3] += av.x*bv.w;
            acc[1][0] += av.y*bv.x; acc[1][1] += av.y*bv.y;
            acc[1][2] += av.y*bv.z; acc[1][3] += av.y*bv.w;
        }
        __syncthreads();
    }

    int gn = n0 + tx*4;
    float b0=0.f,b1=0.f,b2=0.f,b3=0.f;
    if (gn < 2560) { b0=comp_b[gn]; b1=comp_b[gn+1]; b2=comp_b[gn+2]; b3=comp_b[gn+3]; }
    #pragma unroll
    for (int i = 0; i < 2; i++) {
        int orow = s_rm[ty*2 + i];
        if (orow < 0) continue;
        float4 o;
        o.x = acc[i][0] + b0; o.y = acc[i][1] + b1;
        o.z = acc[i][2] + b2; o.w = acc[i][3] + b3;
        *(float4*)(g_UW + (size_t)orow*UWLD + gn) = o;
    }
}

// ---------------------------------------------------------------------------
// Persistent loop: 23 step phases + 22 update-GEMM phases, grid barriers.
// Blocks 0..63 own batch b's tree state in shared memory.
__global__ void __launch_bounds__(NTHR_P, 1)
k_loop(const float* __restrict__ q, const int* __restrict__ length,
       float* __restrict__ out,
       const float* __restrict__ comp_W, const float* __restrict__ comp_b)
{
    const int bid = blockIdx.x;
    const int tid = threadIdx.x;
    unsigned lsense = 0;
    __shared__ float As[2][16][64];   // update-phase tiles (8 KB)
    __shared__ float Bs[2][16][40];   // (5 KB)
    __shared__ int   s_pos[Lsz];
    __shared__ float s_sc[Lsz];
    __shared__ float red[2][4];
    __shared__ int   s_k, s_len;
    __shared__ int   s_rm[Bsz];
    const bool stepB = (bid < Bsz);
    const int b = bid;

    if (stepB) {
        if (tid == 0) { s_len = length[b]; s_k = -1; }
        if (tid < Lsz) s_pos[tid] = b*Lsz + tid;
        if (tid < Lsz-1) s_sc[tid] = g_scores[b*Lsz + tid];  // from k_score_all
    }
    __syncthreads();

    for (int iter = 0; iter < Lsz-1; iter++) {
        if (stepB) {
            int nvalid = s_len - 1 - iter;
            if (iter > 0 && s_k >= 0) {
                int kp = s_k;                       // rescore pairs kp-1, kp
                int half = 0, ht = 0, jj = -1;
                bool act = false;
                float part = 0.f;
                if (tid < 256) {
                    half = tid >> 7;
                    ht   = tid & 127;
                    jj = kp - 1 + half;
                    act = (jj >= 0) && (jj < nvalid);
                    if (act) {
                        int l = s_pos[jj], r = s_pos[jj+1];
                        #pragma unroll
                        for (int s = 0; s < 4; s++) {
                            int t = ht + s*128;
                            float nh, nc; pair_gates(l, r, t, nh, nc);
                            part += nh * q[t];
                        }
                    }
                    #pragma unroll
                    for (int o = 16; o; o >>= 1) part += __shfl_down_sync(0xffffffffu, part, o);
                    if ((ht & 31) == 0) red[half][ht >> 5] = part;
                }
                __syncthreads();
                if (tid < 256 && (tid & 127) == 0 && act)
                    s_sc[jj] = red[half][0] + red[half][1] + red[half][2] + red[half][3];
                __syncthreads();
            }
            // argmax with first-index tie-break (matches jnp.argmax)
            if (tid < 32) {
                float v = (tid < nvalid) ? s_sc[tid] : -1e9f;
                int idx = tid;
                #pragma unroll
                for (int o = 16; o; o >>= 1) {
                    float v2 = __shfl_down_sync(0xffffffffu, v, o);
                    int  i2  = __shfl_down_sync(0xffffffffu, idx, o);
                    if (v2 > v || (v2 == v && i2 < idx)) { v = v2; idx = i2; }
                }
                if (tid == 0) s_k = (nvalid > 0) ? idx : -1;
            }
            __syncthreads();
            int k = s_k;
            if (k >= 0) {
                int l = s_pos[k], r = s_pos[k+1];
                for (int t = tid; t < 512; t += NTHR_P) {
                    float nh, nc; pair_gates(l, r, t, nh, nc);
                    g_HC[(size_t)l*HCLD + t]       = nh;   // merged node reuses left slot
                    g_HC[(size_t)l*HCLD + 512 + t] = nc;
                    g_NH[b*512 + t] = nh;                  // staged for update GEMM
                }
                __syncthreads();
                if (tid == 0) {
                    g_rowmap[b] = l;
                    for (int j = k+1; j < Lsz-1; j++) {    // shift logical lists
                        s_pos[j] = s_pos[j+1];
                        s_sc[j]  = s_sc[j+1];
                    }
                }
            } else {
                if (tid == 0) g_rowmap[b] = -1;            // frozen batch
            }
        }
        grid_bar(lsense);
        if (iter < Lsz-2) {
            gemm_update_phase(bid, comp_W, comp_b, s_rm, As, Bs);
            grid_bar(lsense);
        }
    }

    if (stepB) {
        int slot = s_pos[0];
        for (int t = tid; t < 512; t += NTHR_P)
            out[b*512 + t] = g_HC[(size_t)slot*HCLD + t];
    }
}

// ---------------------------------------------------------------------------
extern "C" void kernel_launch(void* const* d_in, const int* in_sizes, int n_in,
                              void* d_out, int out_size) {
    const float* inp    = (const float*)d_in[0];
    const int*   length = (const int*)  d_in[1];
    const float* word_W = (const float*)d_in[2];
    const float* word_b = (const float*)d_in[3];
    const float* comp_W = (const float*)d_in[4];
    const float* comp_b = (const float*)d_in[5];
    const float* q      = (const float*)d_in[6];
    float* out = (float*)d_out;
    (void)in_sizes; (void)n_in; (void)out_size;

    float *HC = nullptr, *UW = nullptr;
    cudaGetSymbolAddress((void**)&HC, g_HC);
    cudaGetSymbolAddress((void**)&UW, g_UW);

    k_reset<<<1, 1>>>();

    // hc = inp @ word_W.T + word_b  -> HC[slot][h|c]  (128x64 tile, 8x4 micro)
    gemm_nt<128, 64, 8, 4, false, 3><<<dim3(1024/64, NSLOT/128), 256>>>(
        inp, Dsz, word_W, Dsz, word_b, HC, HCLD, Dsz);

    // u|w projections for all 1536 leaf nodes (comp_b folded into u half)
    // 960 blocks, 3/SM resident -> 1.08x wave imbalance
    gemm_nt<128, 64, 8, 4, true, 3><<<dim3(5120/64, NSLOT/128), 256>>>(
        HC, HCLD, comp_W, 0, comp_b, UW, UWLD, Hsz);

    k_score_all<<<dim3(Lsz-1, Bsz), 256>>>(q);

    // persistent loop: all 23 merges + 22 incremental u/w updates
    k_loop<<<GRID_P, NTHR_P>>>(q, length, out, comp_W, comp_b);
}